// round 1
// baseline (speedup 1.0000x reference)
#include <cuda_runtime.h>
#include <stdint.h>

// ---------------------------------------------------------------------------
// SSIM loss: 11x11 Gaussian-window SSIM over (16,3,512,512) fp32 pairs.
// Separable conv, 5 channels fused, f32x2 packed math, one scalar output.
// ---------------------------------------------------------------------------

#define IMG_H   512
#define IMG_W   512
#define PLANES  48            // 16 * 3
#define RAD     5
#define TX      32
#define TY      32
#define INW     42            // TX + 2*RAD
#define INH     42
#define NTHREADS 256
#define NTILES_X 16
#define NTILES_Y 16
#define NBLOCKS  (NTILES_X * NTILES_Y * PLANES)   // 12288
#define NPIX     12582912.0                       // 16*3*512*512

// 1D Gaussian weights, sigma=1.5, normalized (computed in double, rounded).
__device__ __constant__ const float W11_c[11] = {
    0.00102838f, 0.00759876f, 0.03600077f, 0.10936071f, 0.21300554f,
    0.26601172f,
    0.21300554f, 0.10936071f, 0.03600077f, 0.00759876f, 0.00102838f
};

__device__ double g_partial[NBLOCKS];

// ---------- f32x2 packed helpers (Blackwell) ----------
__device__ __forceinline__ unsigned long long pack2(float lo, float hi) {
    unsigned long long r;
    asm("mov.b64 %0, {%1, %2};" : "=l"(r) : "f"(lo), "f"(hi));
    return r;
}
__device__ __forceinline__ void unpack2(unsigned long long v, float &lo, float &hi) {
    asm("mov.b64 {%0, %1}, %2;" : "=f"(lo), "=f"(hi) : "l"(v));
}
__device__ __forceinline__ unsigned long long fma2(unsigned long long a,
                                                   unsigned long long b,
                                                   unsigned long long c) {
    unsigned long long d;
    asm("fma.rn.f32x2 %0, %1, %2, %3;" : "=l"(d) : "l"(a), "l"(b), "l"(c));
    return d;
}
__device__ __forceinline__ unsigned long long mul2(unsigned long long a,
                                                   unsigned long long b) {
    unsigned long long d;
    asm("mul.rn.f32x2 %0, %1, %2;" : "=l"(d) : "l"(a), "l"(b));
    return d;
}

__global__ void __launch_bounds__(NTHREADS)
ssim_main(const float *__restrict__ img1, const float *__restrict__ img2) {
    // (a,b) input pairs packed as f32x2
    __shared__ unsigned long long s_in[INH][INW + 1];   // 42*43*8 = 14448 B
    // horizontal conv results, channel-packed
    __shared__ unsigned long long s_hmu[INH][TX + 1];   // (mu1,mu2)  11088 B
    __shared__ unsigned long long s_hsq[INH][TX + 1];   // (E11,E22)  11088 B
    __shared__ float              s_h12[INH][TX + 1];   // E12         5544 B
    __shared__ float              s_red[8];

    const int tid   = threadIdx.x;
    const int plane = blockIdx.z;
    const size_t base = (size_t)plane * (IMG_H * IMG_W);
    const int x0 = blockIdx.x * TX - RAD;
    const int y0 = blockIdx.y * TY - RAD;

    // ---------------- phase 1: load tile + halo (zero-padded) --------------
    for (int i = tid; i < INH * INW; i += NTHREADS) {
        const int r = i / INW;
        const int c = i - r * INW;
        const int gx = x0 + c;
        const int gy = y0 + r;
        float a = 0.0f, b = 0.0f;
        if ((unsigned)gx < (unsigned)IMG_W && (unsigned)gy < (unsigned)IMG_H) {
            const size_t off = base + (size_t)gy * IMG_W + gx;
            a = img1[off];
            b = img2[off];
        }
        s_in[r][c] = pack2(a, b);
    }
    __syncthreads();

    // packed weight registers
    float W11[11];
    unsigned long long wp[11];
#pragma unroll
    for (int k = 0; k < 11; k++) {
        W11[k] = W11_c[k];
        wp[k]  = pack2(W11[k], W11[k]);
    }

    // ---------------- phase 2: horizontal conv (4 outputs / item) ----------
    // items: 42 rows x 8 groups of 4 output cols
    for (int i = tid; i < INH * 8; i += NTHREADS) {
        const int r  = i >> 3;
        const int c0 = (i & 7) * 4;
        unsigned long long amu[4] = {0, 0, 0, 0};
        unsigned long long asq[4] = {0, 0, 0, 0};
        float              ap[4]  = {0.f, 0.f, 0.f, 0.f};
#pragma unroll
        for (int j = 0; j < 14; j++) {              // input cols c0 .. c0+13
            const unsigned long long v = s_in[r][c0 + j];
            const unsigned long long s = mul2(v, v);
            float a, b;
            unpack2(v, a, b);
            const float p = a * b;
#pragma unroll
            for (int o = 0; o < 4; o++) {
                const int k = j - o;
                if (k >= 0 && k < 11) {
                    amu[o] = fma2(wp[k], v, amu[o]);
                    asq[o] = fma2(wp[k], s, asq[o]);
                    ap[o]  = fmaf(W11[k], p, ap[o]);
                }
            }
        }
#pragma unroll
        for (int o = 0; o < 4; o++) {
            s_hmu[r][c0 + o] = amu[o];
            s_hsq[r][c0 + o] = asq[o];
            s_h12[r][c0 + o] = ap[o];
        }
    }
    __syncthreads();

    // ---------------- phase 3: vertical conv + SSIM (4 rows / thread) -----
    float tsum = 0.0f;
    {
        const int col = tid & 31;
        const int ry0 = (tid >> 5) << 2;            // 8 strips of 4 rows
        unsigned long long amu[4] = {0, 0, 0, 0};
        unsigned long long asq[4] = {0, 0, 0, 0};
        float              ap[4]  = {0.f, 0.f, 0.f, 0.f};
#pragma unroll
        for (int jj = 0; jj < 14; jj++) {           // h rows ry0 .. ry0+13
            const unsigned long long m = s_hmu[ry0 + jj][col];
            const unsigned long long s = s_hsq[ry0 + jj][col];
            const float              p = s_h12[ry0 + jj][col];
#pragma unroll
            for (int o = 0; o < 4; o++) {
                const int k = jj - o;
                if (k >= 0 && k < 11) {
                    amu[o] = fma2(wp[k], m, amu[o]);
                    asq[o] = fma2(wp[k], s, asq[o]);
                    ap[o]  = fmaf(W11[k], p, ap[o]);
                }
            }
        }
        const float C1 = 1e-4f;   // 0.01^2
        const float C2 = 9e-4f;   // 0.03^2
#pragma unroll
        for (int o = 0; o < 4; o++) {
            float mu1, mu2, e11, e22;
            unpack2(amu[o], mu1, mu2);
            unpack2(asq[o], e11, e22);
            const float e12    = ap[o];
            const float mu1mu2 = mu1 * mu2;
            const float mu1sq  = mu1 * mu1;
            const float mu2sq  = mu2 * mu2;
            const float s1  = e11 - mu1sq;
            const float s2  = e22 - mu2sq;
            const float s12 = e12 - mu1mu2;
            const float num = (2.0f * mu1mu2 + C1) * (2.0f * s12 + C2);
            const float den = (mu1sq + mu2sq + C1) * (s1 + s2 + C2);
            tsum += num / den;
        }
    }

    // ---------------- block reduction (deterministic per run) -------------
#pragma unroll
    for (int off = 16; off > 0; off >>= 1)
        tsum += __shfl_down_sync(0xffffffffu, tsum, off);
    if ((tid & 31) == 0) s_red[tid >> 5] = tsum;
    __syncthreads();
    if (tid == 0) {
        float bs = 0.0f;
#pragma unroll
        for (int i = 0; i < 8; i++) bs += s_red[i];
        const int bid = ((int)blockIdx.z * gridDim.y + (int)blockIdx.y) * gridDim.x
                        + (int)blockIdx.x;
        g_partial[bid] = (double)bs;
    }
}

__global__ void ssim_finalize(float *__restrict__ out) {
    __shared__ double sd[256];
    double s = 0.0;
    for (int i = threadIdx.x; i < NBLOCKS; i += 256) s += g_partial[i];
    sd[threadIdx.x] = s;
    __syncthreads();
#pragma unroll
    for (int off = 128; off > 0; off >>= 1) {
        if (threadIdx.x < off) sd[threadIdx.x] += sd[threadIdx.x + off];
        __syncthreads();
    }
    if (threadIdx.x == 0)
        out[0] = (float)(1.0 - sd[0] * (1.0 / NPIX));
}

extern "C" void kernel_launch(void *const *d_in, const int *in_sizes, int n_in,
                              void *d_out, int out_size) {
    (void)in_sizes; (void)n_in; (void)out_size;
    const float *img1 = (const float *)d_in[0];
    const float *img2 = (const float *)d_in[1];
    float *out = (float *)d_out;

    dim3 grid(NTILES_X, NTILES_Y, PLANES);
    ssim_main<<<grid, NTHREADS>>>(img1, img2);
    ssim_finalize<<<1, 256>>>(out);
}